// round 7
// baseline (speedup 1.0000x reference)
#include <cuda_runtime.h>
#include <math.h>

// Problem constants
#define BB 8
#define SS 2048
#define EE 512
#define HH 8
#define DD 64
#define M_TOTAL (BB*SS)      // 16384
#define QKV_LD  (3*EE)       // 1536

// Scratch (device globals: no allocation allowed)
__device__ float g_w[EE * QKV_LD];            // packed [e][p*512 + h*64 + d]
__device__ float g_qkv[(size_t)M_TOTAL * QKV_LD];
__device__ float g_att[(size_t)M_TOTAL * EE];

// ---------------------------------------------------------------------------
// Pack Wq/Wk/Wv [H,E,D] -> g_w [E, 3*512] with col = p*512 + h*64 + d
// ---------------------------------------------------------------------------
__global__ void pack_w_kernel(const float* __restrict__ Wq,
                              const float* __restrict__ Wk,
                              const float* __restrict__ Wv) {
    int tid = blockIdx.x * blockDim.x + threadIdx.x;
    if (tid >= EE * QKV_LD) return;
    int e   = tid / QKV_LD;
    int col = tid % QKV_LD;
    int p = col >> 9;
    int h = (col >> 6) & 7;
    int d = col & 63;
    const float* W = (p == 0) ? Wq : (p == 1) ? Wk : Wv;
    g_w[tid] = W[((size_t)h * EE + e) * DD + d];
}

// ---------------------------------------------------------------------------
// SGEMM: C[M][N] = A[M][K] @ B[K][N] (+ bias). BM=BN=64, BK=32, 256 threads,
// 4x4 register micro-tiles, A staged transposed in smem.
// ---------------------------------------------------------------------------
template<int N_TOTAL, bool BIAS>
__global__ __launch_bounds__(256)
void sgemm_kernel(const float* __restrict__ A, const float* __restrict__ Bm,
                  float* __restrict__ C, const float* __restrict__ bias, int K) {
    const int BM = 64, BN = 64, BK = 32;
    __shared__ __align__(16) float As[BK][BM + 4];   // transposed, pad 68
    __shared__ __align__(16) float Bs[BK][BN];

    int t  = threadIdx.x;
    int ty = t >> 4, tx = t & 15;
    int m0 = blockIdx.y * BM;
    int n0 = blockIdx.x * BN;

    float acc[4][4] = {};

    for (int k0 = 0; k0 < K; k0 += BK) {
        // A tile: 64 rows x 32 cols, stored transposed As[k][m]
        #pragma unroll
        for (int r = 0; r < 2; r++) {
            int f  = t + r * 256;      // 0..511 float4s
            int m  = f >> 3;
            int k4 = f & 7;
            float4 v = *(const float4*)(A + (size_t)(m0 + m) * K + k0 + k4 * 4);
            As[k4 * 4 + 0][m] = v.x;
            As[k4 * 4 + 1][m] = v.y;
            As[k4 * 4 + 2][m] = v.z;
            As[k4 * 4 + 3][m] = v.w;
        }
        // B tile: 32 rows x 64 cols, direct
        #pragma unroll
        for (int r = 0; r < 2; r++) {
            int f  = t + r * 256;
            int kk = f >> 4;
            int n4 = f & 15;
            *(float4*)&Bs[kk][n4 * 4] =
                *(const float4*)(Bm + (size_t)(k0 + kk) * N_TOTAL + n0 + n4 * 4);
        }
        __syncthreads();

        #pragma unroll
        for (int k = 0; k < BK; k++) {
            float4 a4 = *(const float4*)&As[k][ty * 4];
            float4 b4 = *(const float4*)&Bs[k][tx * 4];
            float a[4] = {a4.x, a4.y, a4.z, a4.w};
            float b[4] = {b4.x, b4.y, b4.z, b4.w};
            #pragma unroll
            for (int i = 0; i < 4; i++)
                #pragma unroll
                for (int j = 0; j < 4; j++)
                    acc[i][j] = fmaf(a[i], b[j], acc[i][j]);
        }
        __syncthreads();
    }

    #pragma unroll
    for (int i = 0; i < 4; i++) {
        float4 v = make_float4(acc[i][0], acc[i][1], acc[i][2], acc[i][3]);
        if (BIAS) {
            v.x += bias[n0 + tx * 4 + 0];
            v.y += bias[n0 + tx * 4 + 1];
            v.z += bias[n0 + tx * 4 + 2];
            v.w += bias[n0 + tx * 4 + 3];
        }
        *(float4*)(C + (size_t)(m0 + ty * 4 + i) * N_TOTAL + n0 + tx * 4) = v;
    }
}

// ---------------------------------------------------------------------------
// Flash attention, fp32. One CTA per (b,h, 64-row query block).
// Qt[d][m], Kt[d][n] transposed in smem; Pt[n][m] for the PV GEMM.
// Online softmax; causal key-blocks beyond the diagonal are never visited.
// ---------------------------------------------------------------------------
#define NEG_BIG (-1e30f)

__global__ __launch_bounds__(256)
void attn_kernel() {
    extern __shared__ __align__(16) float smem[];
    float (*Qt)[64] = (float(*)[64])(smem);                 // 4096 floats
    float (*Kt)[64] = (float(*)[64])(smem + 4096);          // 4096
    float (*Pt)[68] = (float(*)[68])(smem + 8192);          // 4352
    float (*Vs)[64] = (float(*)[64])(smem + 12544);         // 4096

    int t  = threadIdx.x;
    int ty = t >> 4, tx = t & 15;
    int qi = gridDim.x - 1 - blockIdx.x;   // longest work first
    int bh = blockIdx.y;
    int b = bh >> 3, h = bh & 7;

    const float* qbase = g_qkv + (size_t)(b * SS) * QKV_LD + h * DD;
    const float* kbase = qbase + EE;
    const float* vbase = qbase + 2 * EE;
    int s0 = qi * 64;

    // Load Q block transposed: Qt[d][m]
    #pragma unroll
    for (int r = 0; r < 4; r++) {
        int f  = t + r * 256;       // 0..1023 float4s
        int m  = f >> 4;
        int d4 = f & 15;
        float4 v = *(const float4*)(qbase + (size_t)(s0 + m) * QKV_LD + d4 * 4);
        Qt[d4 * 4 + 0][m] = v.x;
        Qt[d4 * 4 + 1][m] = v.y;
        Qt[d4 * 4 + 2][m] = v.z;
        Qt[d4 * 4 + 3][m] = v.w;
    }

    float o[4][4] = {};
    float run_max[4], l[4];
    #pragma unroll
    for (int i = 0; i < 4; i++) { run_max[i] = NEG_BIG; l[i] = 0.f; }
    const float scale = 0.125f;   // 1/sqrt(64)

    for (int j = 0; j <= qi; j++) {
        int t0 = j * 64;
        // Load K (transposed) and V (direct)
        #pragma unroll
        for (int r = 0; r < 4; r++) {
            int f  = t + r * 256;
            int n  = f >> 4;
            int d4 = f & 15;
            float4 kv = *(const float4*)(kbase + (size_t)(t0 + n) * QKV_LD + d4 * 4);
            Kt[d4 * 4 + 0][n] = kv.x;
            Kt[d4 * 4 + 1][n] = kv.y;
            Kt[d4 * 4 + 2][n] = kv.z;
            Kt[d4 * 4 + 3][n] = kv.w;
            float4 vv = *(const float4*)(vbase + (size_t)(t0 + n) * QKV_LD + d4 * 4);
            *(float4*)&Vs[n][d4 * 4] = vv;
        }
        __syncthreads();

        // S = Q @ K^T
        float s[4][4] = {};
        #pragma unroll 16
        for (int d = 0; d < 64; d++) {
            float4 q4 = *(const float4*)&Qt[d][ty * 4];
            float4 k4 = *(const float4*)&Kt[d][tx * 4];
            float qa[4] = {q4.x, q4.y, q4.z, q4.w};
            float kb[4] = {k4.x, k4.y, k4.z, k4.w};
            #pragma unroll
            for (int i = 0; i < 4; i++)
                #pragma unroll
                for (int j2 = 0; j2 < 4; j2++)
                    s[i][j2] = fmaf(qa[i], kb[j2], s[i][j2]);
        }

        // scale + causal mask (only the diagonal block has masked entries)
        if (j == qi) {
            #pragma unroll
            for (int i = 0; i < 4; i++)
                #pragma unroll
                for (int j2 = 0; j2 < 4; j2++) {
                    int mg = s0 + ty * 4 + i;
                    int ng = t0 + tx * 4 + j2;
                    s[i][j2] = (ng <= mg) ? s[i][j2] * scale : NEG_BIG;
                }
        } else {
            #pragma unroll
            for (int i = 0; i < 4; i++)
                #pragma unroll
                for (int j2 = 0; j2 < 4; j2++)
                    s[i][j2] *= scale;
        }

        // Online softmax update (row groups = 16 lanes sharing ty)
        #pragma unroll
        for (int i = 0; i < 4; i++) {
            float rm = fmaxf(fmaxf(s[i][0], s[i][1]), fmaxf(s[i][2], s[i][3]));
            #pragma unroll
            for (int off = 8; off > 0; off >>= 1)
                rm = fmaxf(rm, __shfl_xor_sync(0xffffffffu, rm, off, 16));
            float nm   = fmaxf(run_max[i], rm);
            float corr = __expf(run_max[i] - nm);
            run_max[i] = nm;
            float rs = 0.f;
            #pragma unroll
            for (int j2 = 0; j2 < 4; j2++) {
                float p = __expf(s[i][j2] - nm);
                s[i][j2] = p;
                rs += p;
            }
            #pragma unroll
            for (int off = 8; off > 0; off >>= 1)
                rs += __shfl_xor_sync(0xffffffffu, rs, off, 16);
            l[i] = l[i] * corr + rs;
            #pragma unroll
            for (int j2 = 0; j2 < 4; j2++)
                o[i][j2] *= corr;
        }

        // Write P transposed: Pt[n][m]
        #pragma unroll
        for (int j2 = 0; j2 < 4; j2++)
            *(float4*)&Pt[tx * 4 + j2][ty * 4] =
                make_float4(s[0][j2], s[1][j2], s[2][j2], s[3][j2]);
        __syncthreads();

        // O += P @ V
        #pragma unroll 16
        for (int n = 0; n < 64; n++) {
            float4 p4 = *(const float4*)&Pt[n][ty * 4];
            float4 v4 = *(const float4*)&Vs[n][tx * 4];
            float pa[4] = {p4.x, p4.y, p4.z, p4.w};
            float vb[4] = {v4.x, v4.y, v4.z, v4.w};
            #pragma unroll
            for (int i = 0; i < 4; i++)
                #pragma unroll
                for (int j2 = 0; j2 < 4; j2++)
                    o[i][j2] = fmaf(pa[i], vb[j2], o[i][j2]);
        }
        __syncthreads();
    }

    // Normalize and store to g_att [(b*S+s)][h*64+d]
    #pragma unroll
    for (int i = 0; i < 4; i++) {
        float inv = 1.0f / l[i];
        float4 v = make_float4(o[i][0] * inv, o[i][1] * inv,
                               o[i][2] * inv, o[i][3] * inv);
        *(float4*)(g_att + (size_t)(b * SS + s0 + ty * 4 + i) * EE + h * DD + tx * 4) = v;
    }
}

// Shared mem bytes for attn_kernel
#define ATTN_SMEM ((4096 + 4096 + 4352 + 4096) * 4)

// ---------------------------------------------------------------------------
extern "C" void kernel_launch(void* const* d_in, const int* in_sizes, int n_in,
                              void* d_out, int out_size) {
    const float* x  = (const float*)d_in[0];
    const float* Wq = (const float*)d_in[1];
    const float* Wk = (const float*)d_in[2];
    const float* Wv = (const float*)d_in[3];
    const float* Wp = (const float*)d_in[4];
    const float* bp = (const float*)d_in[5];
    float* out = (float*)d_out;

    float *p_w, *p_qkv, *p_att;
    cudaGetSymbolAddress((void**)&p_w,   g_w);
    cudaGetSymbolAddress((void**)&p_qkv, g_qkv);
    cudaGetSymbolAddress((void**)&p_att, g_att);

    // 1) pack weights
    pack_w_kernel<<<(EE * QKV_LD + 255) / 256, 256>>>(Wq, Wk, Wv);

    // 2) fused QKV projection: [16384x512] @ [512x1536]
    sgemm_kernel<QKV_LD, false><<<dim3(QKV_LD / 64, M_TOTAL / 64), 256>>>(
        x, p_w, p_qkv, nullptr, EE);

    // 3) flash attention
    cudaFuncSetAttribute(attn_kernel,
                         cudaFuncAttributeMaxDynamicSharedMemorySize, ATTN_SMEM);
    attn_kernel<<<dim3(SS / 64, BB * HH), 256, ATTN_SMEM>>>();

    // 4) output projection + bias: [16384x512] @ [512x512]
    sgemm_kernel<EE, true><<<dim3(EE / 64, M_TOTAL / 64), 256>>>(
        p_att, Wp, out, bp, EE);
}

// round 8
// speedup vs baseline: 1.0082x; 1.0082x over previous
#include <cuda_runtime.h>
#include <math.h>

// Problem constants
#define BB 8
#define SS 2048
#define EE 512
#define HH 8
#define DD 64
#define M_TOTAL (BB*SS)      // 16384
#define QKV_LD  (3*EE)       // 1536

// Scratch (device globals: no allocation allowed)
__device__ float g_w[EE * QKV_LD];            // packed [e][p*512 + h*64 + d]
__device__ float g_qkv[(size_t)M_TOTAL * QKV_LD];
__device__ float g_att[(size_t)M_TOTAL * EE];

// ---------------------------------------------------------------------------
// Pack Wq/Wk/Wv [H,E,D] -> g_w [E, 3*512] with col = p*512 + h*64 + d
// ---------------------------------------------------------------------------
__global__ void pack_w_kernel(const float* __restrict__ Wq,
                              const float* __restrict__ Wk,
                              const float* __restrict__ Wv) {
    int tid = blockIdx.x * blockDim.x + threadIdx.x;
    if (tid >= EE * QKV_LD) return;
    int e   = tid / QKV_LD;
    int col = tid % QKV_LD;
    int p = col >> 9;
    int h = (col >> 6) & 7;
    int d = col & 63;
    const float* W = (p == 0) ? Wq : (p == 1) ? Wk : Wv;
    g_w[tid] = W[((size_t)h * EE + e) * DD + d];
}

// ---------------------------------------------------------------------------
// SGEMM: C[M][N] = A[M][K] @ B[K][N] (+ bias). BM=BN=64, BK=32, 256 threads,
// 4x4 register micro-tiles, A staged transposed in smem.
// ---------------------------------------------------------------------------
template<int N_TOTAL, bool BIAS>
__global__ __launch_bounds__(256)
void sgemm_kernel(const float* __restrict__ A, const float* __restrict__ Bm,
                  float* __restrict__ C, const float* __restrict__ bias, int K) {
    const int BM = 64, BN = 64, BK = 32;
    __shared__ __align__(16) float As[BK][BM + 4];   // transposed, pad 68
    __shared__ __align__(16) float Bs[BK][BN];

    int t  = threadIdx.x;
    int ty = t >> 4, tx = t & 15;
    int m0 = blockIdx.y * BM;
    int n0 = blockIdx.x * BN;

    float acc[4][4] = {};

    for (int k0 = 0; k0 < K; k0 += BK) {
        // A tile: 64 rows x 32 cols, stored transposed As[k][m]
        #pragma unroll
        for (int r = 0; r < 2; r++) {
            int f  = t + r * 256;      // 0..511 float4s
            int m  = f >> 3;
            int k4 = f & 7;
            float4 v = *(const float4*)(A + (size_t)(m0 + m) * K + k0 + k4 * 4);
            As[k4 * 4 + 0][m] = v.x;
            As[k4 * 4 + 1][m] = v.y;
            As[k4 * 4 + 2][m] = v.z;
            As[k4 * 4 + 3][m] = v.w;
        }
        // B tile: 32 rows x 64 cols, direct
        #pragma unroll
        for (int r = 0; r < 2; r++) {
            int f  = t + r * 256;
            int kk = f >> 4;
            int n4 = f & 15;
            *(float4*)&Bs[kk][n4 * 4] =
                *(const float4*)(Bm + (size_t)(k0 + kk) * N_TOTAL + n0 + n4 * 4);
        }
        __syncthreads();

        #pragma unroll
        for (int k = 0; k < BK; k++) {
            float4 a4 = *(const float4*)&As[k][ty * 4];
            float4 b4 = *(const float4*)&Bs[k][tx * 4];
            float a[4] = {a4.x, a4.y, a4.z, a4.w};
            float b[4] = {b4.x, b4.y, b4.z, b4.w};
            #pragma unroll
            for (int i = 0; i < 4; i++)
                #pragma unroll
                for (int j = 0; j < 4; j++)
                    acc[i][j] = fmaf(a[i], b[j], acc[i][j]);
        }
        __syncthreads();
    }

    #pragma unroll
    for (int i = 0; i < 4; i++) {
        float4 v = make_float4(acc[i][0], acc[i][1], acc[i][2], acc[i][3]);
        if (BIAS) {
            v.x += bias[n0 + tx * 4 + 0];
            v.y += bias[n0 + tx * 4 + 1];
            v.z += bias[n0 + tx * 4 + 2];
            v.w += bias[n0 + tx * 4 + 3];
        }
        *(float4*)(C + (size_t)(m0 + ty * 4 + i) * N_TOTAL + n0 + tx * 4) = v;
    }
}

// ---------------------------------------------------------------------------
// Flash attention, fp32. One CTA per (b,h, 64-row query block).
// Qt[d][m], Kt[d][n] transposed in smem; Pt[n][m] for the PV GEMM.
// Online softmax; causal key-blocks beyond the diagonal are never visited.
// ---------------------------------------------------------------------------
#define NEG_BIG (-1e30f)

__global__ __launch_bounds__(256)
void attn_kernel() {
    extern __shared__ __align__(16) float smem[];
    float (*Qt)[64] = (float(*)[64])(smem);                 // 4096 floats
    float (*Kt)[64] = (float(*)[64])(smem + 4096);          // 4096
    float (*Pt)[68] = (float(*)[68])(smem + 8192);          // 4352
    float (*Vs)[64] = (float(*)[64])(smem + 12544);         // 4096

    int t  = threadIdx.x;
    int ty = t >> 4, tx = t & 15;
    int qi = gridDim.x - 1 - blockIdx.x;   // longest work first
    int bh = blockIdx.y;
    int b = bh >> 3, h = bh & 7;

    const float* qbase = g_qkv + (size_t)(b * SS) * QKV_LD + h * DD;
    const float* kbase = qbase + EE;
    const float* vbase = qbase + 2 * EE;
    int s0 = qi * 64;

    // Load Q block transposed: Qt[d][m]
    #pragma unroll
    for (int r = 0; r < 4; r++) {
        int f  = t + r * 256;       // 0..1023 float4s
        int m  = f >> 4;
        int d4 = f & 15;
        float4 v = *(const float4*)(qbase + (size_t)(s0 + m) * QKV_LD + d4 * 4);
        Qt[d4 * 4 + 0][m] = v.x;
        Qt[d4 * 4 + 1][m] = v.y;
        Qt[d4 * 4 + 2][m] = v.z;
        Qt[d4 * 4 + 3][m] = v.w;
    }

    float o[4][4] = {};
    float run_max[4], l[4];
    #pragma unroll
    for (int i = 0; i < 4; i++) { run_max[i] = NEG_BIG; l[i] = 0.f; }
    const float scale = 0.125f;   // 1/sqrt(64)

    for (int j = 0; j <= qi; j++) {
        int t0 = j * 64;
        // Load K (transposed) and V (direct)
        #pragma unroll
        for (int r = 0; r < 4; r++) {
            int f  = t + r * 256;
            int n  = f >> 4;
            int d4 = f & 15;
            float4 kv = *(const float4*)(kbase + (size_t)(t0 + n) * QKV_LD + d4 * 4);
            Kt[d4 * 4 + 0][n] = kv.x;
            Kt[d4 * 4 + 1][n] = kv.y;
            Kt[d4 * 4 + 2][n] = kv.z;
            Kt[d4 * 4 + 3][n] = kv.w;
            float4 vv = *(const float4*)(vbase + (size_t)(t0 + n) * QKV_LD + d4 * 4);
            *(float4*)&Vs[n][d4 * 4] = vv;
        }
        __syncthreads();

        // S = Q @ K^T
        float s[4][4] = {};
        #pragma unroll 16
        for (int d = 0; d < 64; d++) {
            float4 q4 = *(const float4*)&Qt[d][ty * 4];
            float4 k4 = *(const float4*)&Kt[d][tx * 4];
            float qa[4] = {q4.x, q4.y, q4.z, q4.w};
            float kb[4] = {k4.x, k4.y, k4.z, k4.w};
            #pragma unroll
            for (int i = 0; i < 4; i++)
                #pragma unroll
                for (int j2 = 0; j2 < 4; j2++)
                    s[i][j2] = fmaf(qa[i], kb[j2], s[i][j2]);
        }

        // scale + causal mask (only the diagonal block has masked entries)
        if (j == qi) {
            #pragma unroll
            for (int i = 0; i < 4; i++)
                #pragma unroll
                for (int j2 = 0; j2 < 4; j2++) {
                    int mg = s0 + ty * 4 + i;
                    int ng = t0 + tx * 4 + j2;
                    s[i][j2] = (ng <= mg) ? s[i][j2] * scale : NEG_BIG;
                }
        } else {
            #pragma unroll
            for (int i = 0; i < 4; i++)
                #pragma unroll
                for (int j2 = 0; j2 < 4; j2++)
                    s[i][j2] *= scale;
        }

        // Online softmax update (row groups = 16 lanes sharing ty)
        #pragma unroll
        for (int i = 0; i < 4; i++) {
            float rm = fmaxf(fmaxf(s[i][0], s[i][1]), fmaxf(s[i][2], s[i][3]));
            #pragma unroll
            for (int off = 8; off > 0; off >>= 1)
                rm = fmaxf(rm, __shfl_xor_sync(0xffffffffu, rm, off, 16));
            float nm   = fmaxf(run_max[i], rm);
            float corr = __expf(run_max[i] - nm);
            run_max[i] = nm;
            float rs = 0.f;
            #pragma unroll
            for (int j2 = 0; j2 < 4; j2++) {
                float p = __expf(s[i][j2] - nm);
                s[i][j2] = p;
                rs += p;
            }
            #pragma unroll
            for (int off = 8; off > 0; off >>= 1)
                rs += __shfl_xor_sync(0xffffffffu, rs, off, 16);
            l[i] = l[i] * corr + rs;
            #pragma unroll
            for (int j2 = 0; j2 < 4; j2++)
                o[i][j2] *= corr;
        }

        // Write P transposed: Pt[n][m]
        #pragma unroll
        for (int j2 = 0; j2 < 4; j2++)
            *(float4*)&Pt[tx * 4 + j2][ty * 4] =
                make_float4(s[0][j2], s[1][j2], s[2][j2], s[3][j2]);
        __syncthreads();

        // O += P @ V
        #pragma unroll 16
        for (int n = 0; n < 64; n++) {
            float4 p4 = *(const float4*)&Pt[n][ty * 4];
            float4 v4 = *(const float4*)&Vs[n][tx * 4];
            float pa[4] = {p4.x, p4.y, p4.z, p4.w};
            float vb[4] = {v4.x, v4.y, v4.z, v4.w};
            #pragma unroll
            for (int i = 0; i < 4; i++)
                #pragma unroll
                for (int j2 = 0; j2 < 4; j2++)
                    o[i][j2] = fmaf(pa[i], vb[j2], o[i][j2]);
        }
        __syncthreads();
    }

    // Normalize and store to g_att [(b*S+s)][h*64+d]
    #pragma unroll
    for (int i = 0; i < 4; i++) {
        float inv = 1.0f / l[i];
        float4 v = make_float4(o[i][0] * inv, o[i][1] * inv,
                               o[i][2] * inv, o[i][3] * inv);
        *(float4*)(g_att + (size_t)(b * SS + s0 + ty * 4 + i) * EE + h * DD + tx * 4) = v;
    }
}

// Shared mem bytes for attn_kernel
#define ATTN_SMEM ((4096 + 4096 + 4352 + 4096) * 4)

// ---------------------------------------------------------------------------
extern "C" void kernel_launch(void* const* d_in, const int* in_sizes, int n_in,
                              void* d_out, int out_size) {
    const float* x  = (const float*)d_in[0];
    const float* Wq = (const float*)d_in[1];
    const float* Wk = (const float*)d_in[2];
    const float* Wv = (const float*)d_in[3];
    const float* Wp = (const float*)d_in[4];
    const float* bp = (const float*)d_in[5];
    float* out = (float*)d_out;

    float *p_w, *p_qkv, *p_att;
    cudaGetSymbolAddress((void**)&p_w,   g_w);
    cudaGetSymbolAddress((void**)&p_qkv, g_qkv);
    cudaGetSymbolAddress((void**)&p_att, g_att);

    // 1) pack weights
    pack_w_kernel<<<(EE * QKV_LD + 255) / 256, 256>>>(Wq, Wk, Wv);

    // 2) fused QKV projection: [16384x512] @ [512x1536]
    sgemm_kernel<QKV_LD, false><<<dim3(QKV_LD / 64, M_TOTAL / 64), 256>>>(
        x, p_w, p_qkv, nullptr, EE);

    // 3) flash attention
    cudaFuncSetAttribute(attn_kernel,
                         cudaFuncAttributeMaxDynamicSharedMemorySize, ATTN_SMEM);
    attn_kernel<<<dim3(SS / 64, BB * HH), 256, ATTN_SMEM>>>();

    // 4) output projection + bias: [16384x512] @ [512x512]
    sgemm_kernel<EE, true><<<dim3(EE / 64, M_TOTAL / 64), 256>>>(
        p_att, Wp, out, bp, EE);
}

// round 9
// speedup vs baseline: 1.0142x; 1.0059x over previous
#include <cuda_runtime.h>
#include <math.h>

// Problem constants
#define BB 8
#define SS 2048
#define EE 512
#define HH 8
#define DD 64
#define M_TOTAL (BB*SS)      // 16384
#define QKV_LD  (3*EE)       // 1536

// Scratch (device globals: no allocation allowed)
__device__ float g_w[EE * QKV_LD];            // packed [e][p*512 + h*64 + d]
__device__ float g_qkv[(size_t)M_TOTAL * QKV_LD];
__device__ float g_att[(size_t)M_TOTAL * EE];

// ---------------------------------------------------------------------------
// Pack Wq/Wk/Wv [H,E,D] -> g_w [E, 3*512] with col = p*512 + h*64 + d
// ---------------------------------------------------------------------------
__global__ void pack_w_kernel(const float* __restrict__ Wq,
                              const float* __restrict__ Wk,
                              const float* __restrict__ Wv) {
    int tid = blockIdx.x * blockDim.x + threadIdx.x;
    if (tid >= EE * QKV_LD) return;
    int e   = tid / QKV_LD;
    int col = tid % QKV_LD;
    int p = col >> 9;
    int h = (col >> 6) & 7;
    int d = col & 63;
    const float* W = (p == 0) ? Wq : (p == 1) ? Wk : Wv;
    g_w[tid] = W[((size_t)h * EE + e) * DD + d];
}

// ---------------------------------------------------------------------------
// SGEMM: C[M][N] = A[M][K] @ B[K][N] (+ bias). BM=BN=64, BK=32, 256 threads,
// 4x4 register micro-tiles, A staged transposed in smem.
// ---------------------------------------------------------------------------
template<int N_TOTAL, bool BIAS>
__global__ __launch_bounds__(256)
void sgemm_kernel(const float* __restrict__ A, const float* __restrict__ Bm,
                  float* __restrict__ C, const float* __restrict__ bias, int K) {
    const int BM = 64, BN = 64, BK = 32;
    __shared__ __align__(16) float As[BK][BM + 4];   // transposed, pad 68
    __shared__ __align__(16) float Bs[BK][BN];

    int t  = threadIdx.x;
    int ty = t >> 4, tx = t & 15;
    int m0 = blockIdx.y * BM;
    int n0 = blockIdx.x * BN;

    float acc[4][4] = {};

    for (int k0 = 0; k0 < K; k0 += BK) {
        // A tile: 64 rows x 32 cols, stored transposed As[k][m]
        #pragma unroll
        for (int r = 0; r < 2; r++) {
            int f  = t + r * 256;      // 0..511 float4s
            int m  = f >> 3;
            int k4 = f & 7;
            float4 v = *(const float4*)(A + (size_t)(m0 + m) * K + k0 + k4 * 4);
            As[k4 * 4 + 0][m] = v.x;
            As[k4 * 4 + 1][m] = v.y;
            As[k4 * 4 + 2][m] = v.z;
            As[k4 * 4 + 3][m] = v.w;
        }
        // B tile: 32 rows x 64 cols, direct
        #pragma unroll
        for (int r = 0; r < 2; r++) {
            int f  = t + r * 256;
            int kk = f >> 4;
            int n4 = f & 15;
            *(float4*)&Bs[kk][n4 * 4] =
                *(const float4*)(Bm + (size_t)(k0 + kk) * N_TOTAL + n0 + n4 * 4);
        }
        __syncthreads();

        #pragma unroll
        for (int k = 0; k < BK; k++) {
            float4 a4 = *(const float4*)&As[k][ty * 4];
            float4 b4 = *(const float4*)&Bs[k][tx * 4];
            float a[4] = {a4.x, a4.y, a4.z, a4.w};
            float b[4] = {b4.x, b4.y, b4.z, b4.w};
            #pragma unroll
            for (int i = 0; i < 4; i++)
                #pragma unroll
                for (int j = 0; j < 4; j++)
                    acc[i][j] = fmaf(a[i], b[j], acc[i][j]);
        }
        __syncthreads();
    }

    #pragma unroll
    for (int i = 0; i < 4; i++) {
        float4 v = make_float4(acc[i][0], acc[i][1], acc[i][2], acc[i][3]);
        if (BIAS) {
            v.x += bias[n0 + tx * 4 + 0];
            v.y += bias[n0 + tx * 4 + 1];
            v.z += bias[n0 + tx * 4 + 2];
            v.w += bias[n0 + tx * 4 + 3];
        }
        *(float4*)(C + (size_t)(m0 + ty * 4 + i) * N_TOTAL + n0 + tx * 4) = v;
    }
}

// ---------------------------------------------------------------------------
// Flash attention, fp32. One CTA per (b,h, 64-row query block).
// Qt[d][m], Kt[d][n] transposed in smem; Pt[n][m] for the PV GEMM.
// Online softmax; causal key-blocks beyond the diagonal are never visited.
// ---------------------------------------------------------------------------
#define NEG_BIG (-1e30f)

__global__ __launch_bounds__(256)
void attn_kernel() {
    extern __shared__ __align__(16) float smem[];
    float (*Qt)[64] = (float(*)[64])(smem);                 // 4096 floats
    float (*Kt)[64] = (float(*)[64])(smem + 4096);          // 4096
    float (*Pt)[68] = (float(*)[68])(smem + 8192);          // 4352
    float (*Vs)[64] = (float(*)[64])(smem + 12544);         // 4096

    int t  = threadIdx.x;
    int ty = t >> 4, tx = t & 15;
    int qi = gridDim.x - 1 - blockIdx.x;   // longest work first
    int bh = blockIdx.y;
    int b = bh >> 3, h = bh & 7;

    const float* qbase = g_qkv + (size_t)(b * SS) * QKV_LD + h * DD;
    const float* kbase = qbase + EE;
    const float* vbase = qbase + 2 * EE;
    int s0 = qi * 64;

    // Load Q block transposed: Qt[d][m]
    #pragma unroll
    for (int r = 0; r < 4; r++) {
        int f  = t + r * 256;       // 0..1023 float4s
        int m  = f >> 4;
        int d4 = f & 15;
        float4 v = *(const float4*)(qbase + (size_t)(s0 + m) * QKV_LD + d4 * 4);
        Qt[d4 * 4 + 0][m] = v.x;
        Qt[d4 * 4 + 1][m] = v.y;
        Qt[d4 * 4 + 2][m] = v.z;
        Qt[d4 * 4 + 3][m] = v.w;
    }

    float o[4][4] = {};
    float run_max[4], l[4];
    #pragma unroll
    for (int i = 0; i < 4; i++) { run_max[i] = NEG_BIG; l[i] = 0.f; }
    const float scale = 0.125f;   // 1/sqrt(64)

    for (int j = 0; j <= qi; j++) {
        int t0 = j * 64;
        // Load K (transposed) and V (direct)
        #pragma unroll
        for (int r = 0; r < 4; r++) {
            int f  = t + r * 256;
            int n  = f >> 4;
            int d4 = f & 15;
            float4 kv = *(const float4*)(kbase + (size_t)(t0 + n) * QKV_LD + d4 * 4);
            Kt[d4 * 4 + 0][n] = kv.x;
            Kt[d4 * 4 + 1][n] = kv.y;
            Kt[d4 * 4 + 2][n] = kv.z;
            Kt[d4 * 4 + 3][n] = kv.w;
            float4 vv = *(const float4*)(vbase + (size_t)(t0 + n) * QKV_LD + d4 * 4);
            *(float4*)&Vs[n][d4 * 4] = vv;
        }
        __syncthreads();

        // S = Q @ K^T
        float s[4][4] = {};
        #pragma unroll 16
        for (int d = 0; d < 64; d++) {
            float4 q4 = *(const float4*)&Qt[d][ty * 4];
            float4 k4 = *(const float4*)&Kt[d][tx * 4];
            float qa[4] = {q4.x, q4.y, q4.z, q4.w};
            float kb[4] = {k4.x, k4.y, k4.z, k4.w};
            #pragma unroll
            for (int i = 0; i < 4; i++)
                #pragma unroll
                for (int j2 = 0; j2 < 4; j2++)
                    s[i][j2] = fmaf(qa[i], kb[j2], s[i][j2]);
        }

        // scale + causal mask (only the diagonal block has masked entries)
        if (j == qi) {
            #pragma unroll
            for (int i = 0; i < 4; i++)
                #pragma unroll
                for (int j2 = 0; j2 < 4; j2++) {
                    int mg = s0 + ty * 4 + i;
                    int ng = t0 + tx * 4 + j2;
                    s[i][j2] = (ng <= mg) ? s[i][j2] * scale : NEG_BIG;
                }
        } else {
            #pragma unroll
            for (int i = 0; i < 4; i++)
                #pragma unroll
                for (int j2 = 0; j2 < 4; j2++)
                    s[i][j2] *= scale;
        }

        // Online softmax update (row groups = 16 lanes sharing ty)
        #pragma unroll
        for (int i = 0; i < 4; i++) {
            float rm = fmaxf(fmaxf(s[i][0], s[i][1]), fmaxf(s[i][2], s[i][3]));
            #pragma unroll
            for (int off = 8; off > 0; off >>= 1)
                rm = fmaxf(rm, __shfl_xor_sync(0xffffffffu, rm, off, 16));
            float nm   = fmaxf(run_max[i], rm);
            float corr = __expf(run_max[i] - nm);
            run_max[i] = nm;
            float rs = 0.f;
            #pragma unroll
            for (int j2 = 0; j2 < 4; j2++) {
                float p = __expf(s[i][j2] - nm);
                s[i][j2] = p;
                rs += p;
            }
            #pragma unroll
            for (int off = 8; off > 0; off >>= 1)
                rs += __shfl_xor_sync(0xffffffffu, rs, off, 16);
            l[i] = l[i] * corr + rs;
            #pragma unroll
            for (int j2 = 0; j2 < 4; j2++)
                o[i][j2] *= corr;
        }

        // Write P transposed: Pt[n][m]
        #pragma unroll
        for (int j2 = 0; j2 < 4; j2++)
            *(float4*)&Pt[tx * 4 + j2][ty * 4] =
                make_float4(s[0][j2], s[1][j2], s[2][j2], s[3][j2]);
        __syncthreads();

        // O += P @ V
        #pragma unroll 16
        for (int n = 0; n < 64; n++) {
            float4 p4 = *(const float4*)&Pt[n][ty * 4];
            float4 v4 = *(const float4*)&Vs[n][tx * 4];
            float pa[4] = {p4.x, p4.y, p4.z, p4.w};
            float vb[4] = {v4.x, v4.y, v4.z, v4.w};
            #pragma unroll
            for (int i = 0; i < 4; i++)
                #pragma unroll
                for (int j2 = 0; j2 < 4; j2++)
                    o[i][j2] = fmaf(pa[i], vb[j2], o[i][j2]);
        }
        __syncthreads();
    }

    // Normalize and store to g_att [(b*S+s)][h*64+d]
    #pragma unroll
    for (int i = 0; i < 4; i++) {
        float inv = 1.0f / l[i];
        float4 v = make_float4(o[i][0] * inv, o[i][1] * inv,
                               o[i][2] * inv, o[i][3] * inv);
        *(float4*)(g_att + (size_t)(b * SS + s0 + ty * 4 + i) * EE + h * DD + tx * 4) = v;
    }
}

// Shared mem bytes for attn_kernel
#define ATTN_SMEM ((4096 + 4096 + 4352 + 4096) * 4)

// ---------------------------------------------------------------------------
extern "C" void kernel_launch(void* const* d_in, const int* in_sizes, int n_in,
                              void* d_out, int out_size) {
    const float* x  = (const float*)d_in[0];
    const float* Wq = (const float*)d_in[1];
    const float* Wk = (const float*)d_in[2];
    const float* Wv = (const float*)d_in[3];
    const float* Wp = (const float*)d_in[4];
    const float* bp = (const float*)d_in[5];
    float* out = (float*)d_out;

    float *p_w, *p_qkv, *p_att;
    cudaGetSymbolAddress((void**)&p_w,   g_w);
    cudaGetSymbolAddress((void**)&p_qkv, g_qkv);
    cudaGetSymbolAddress((void**)&p_att, g_att);

    // 1) pack weights
    pack_w_kernel<<<(EE * QKV_LD + 255) / 256, 256>>>(Wq, Wk, Wv);

    // 2) fused QKV projection: [16384x512] @ [512x1536]
    sgemm_kernel<QKV_LD, false><<<dim3(QKV_LD / 64, M_TOTAL / 64), 256>>>(
        x, p_w, p_qkv, nullptr, EE);

    // 3) flash attention
    cudaFuncSetAttribute(attn_kernel,
                         cudaFuncAttributeMaxDynamicSharedMemorySize, ATTN_SMEM);
    attn_kernel<<<dim3(SS / 64, BB * HH), 256, ATTN_SMEM>>>();

    // 4) output projection + bias: [16384x512] @ [512x512]
    sgemm_kernel<EE, true><<<dim3(EE / 64, M_TOTAL / 64), 256>>>(
        p_att, Wp, out, bp, EE);
}